// round 1
// baseline (speedup 1.0000x reference)
#include <cuda_runtime.h>
#include <math.h>

// ---------------------------------------------------------------------------
// Problem constants
// ---------------------------------------------------------------------------
#define HH   128
#define WW   128
#define BB   64
#define TT   5
#define PIX  (HH*WW)        // 16384 pixels per image
#define TW   32             // tile width  (threads x)
#define TH   8              // tile height (threads y)  -> 256 threads/block

#define NSPLIT 256          // split-K slices for dense1
#define KS     256          // K per slice (256*256 = 65536)

// ---------------------------------------------------------------------------
// Static device scratch (no allocations allowed)
// ---------------------------------------------------------------------------
__device__ float4 g_seqA[BB*TT*PIX];    // layer1 output (BN applied), (B,T,H,W,4)
__device__ float4 g_seqB[BB*TT*PIX];    // layer2 output (BN applied)
__device__ float4 g_hA[BB*PIX];         // recurrent h double-buffer
__device__ float4 g_hB[BB*PIX];
__device__ float4 g_cS[BB*PIX];         // cell state (in-place safe: own-pixel only)
__device__ float4 g_hbn[BB*PIX];        // lrelu(bn(h_last))  == flattened (B,65536)
__device__ float  g_part[NSPLIT*BB*128];// dense1 split-K partials
__device__ float  g_d1[BB*128];
__device__ float  g_d2[BB*128];
__device__ float  g_d3[BB*128];

// ---------------------------------------------------------------------------
// Fast activations (abs err ~1e-7 — far below the 1e-3 gate)
// ---------------------------------------------------------------------------
__device__ __forceinline__ float sigf(float x) {
    return __fdividef(1.0f, 1.0f + __expf(-x));
}
__device__ __forceinline__ float tanhfast(float x) {
    float e = __expf(-2.0f * fabsf(x));
    float r = __fdividef(1.0f - e, 1.0f + e);
    return copysignf(r, x);
}
__device__ __forceinline__ float lreluf(float x) { return x > 0.0f ? x : 0.3f * x; }

// ---------------------------------------------------------------------------
// One ConvLSTM2D timestep (fused: x-conv + h-conv + gates + state + BN write)
//   CINSRC : input channels of x (3 for layer1, 4 for layers 2/3)
//   FIRST  : t==0 -> h=c=0, skip h-conv and state reads
//   MODE   : 0 = no seq write, 1 = write bn(h) to seq_out, 2 = write lrelu(bn(h))
// x layout: (B, ..., H, W, CINSRC) with batch stride x_pxb pixels; xin already
// offset to timestep t. h tiles are double-buffered (hin read / hout write)
// because halo reads cross block boundaries.
// ---------------------------------------------------------------------------
template<int CINSRC, bool FIRST, int MODE>
__global__ __launch_bounds__(256)
void lstm_step(const float* __restrict__ xin, int x_pxb,
               const float* __restrict__ wx, const float* __restrict__ wh,
               const float* __restrict__ bias,
               const float* __restrict__ bng, const float* __restrict__ bnb,
               const float* __restrict__ bnm, const float* __restrict__ bnv,
               const float4* __restrict__ hin, float4* __restrict__ hout,
               float4* __restrict__ seq_out, int s_pxb)
{
    __shared__ float4 s_wx4[144];            // [tap][ci(4)][j(4)] -> 16 couts, ci padded
    __shared__ float4 s_wh4[144];
    __shared__ float  s_bias[16];
    __shared__ float  s_scale[4], s_shift[4];
    __shared__ float4 s_xt[TH+2][TW+2];
    __shared__ float4 s_ht[TH+2][TW+2];

    const int tid = threadIdx.x;
    const int b   = blockIdx.z;
    const int ty0 = blockIdx.y * TH;
    const int tx0 = blockIdx.x * TW;

    // stage weights (pad ci=3 with zeros for CINSRC==3; those FMAs are skipped)
    {
        float* s_wxf = (float*)s_wx4;
        for (int i = tid; i < 576; i += 256) {
            int tap = i >> 6, r = i & 63, ci = r >> 4, co = r & 15;
            s_wxf[i] = (ci < CINSRC) ? wx[(tap*CINSRC + ci)*16 + co] : 0.0f;
        }
        if (!FIRST) {
            float* s_whf = (float*)s_wh4;
            for (int i = tid; i < 576; i += 256) s_whf[i] = wh[i];
        }
        if (tid < 16) s_bias[tid] = bias[tid];
        if (MODE != 0 && tid < 4) {
            float sc = bng[tid] * rsqrtf(bnv[tid] + 1e-3f);
            s_scale[tid] = sc;
            s_shift[tid] = bnb[tid] - bnm[tid]*sc;
        }
    }

    // stage input / h tiles with halo (zero-padded SAME conv)
    const float4* x4 = reinterpret_cast<const float4*>(xin);
    for (int i = tid; i < (TH+2)*(TW+2); i += 256) {
        int ly = i / (TW+2), lx = i % (TW+2);
        int gy = ty0 + ly - 1, gx = tx0 + lx - 1;
        bool ok = (gy >= 0) && (gy < HH) && (gx >= 0) && (gx < WW);
        float4 xv = make_float4(0.f,0.f,0.f,0.f);
        float4 hv = make_float4(0.f,0.f,0.f,0.f);
        if (ok) {
            if (CINSRC == 4) {
                xv = x4[(long)b*x_pxb + gy*WW + gx];
            } else {
                const float* p = xin + ((long)b*x_pxb + gy*WW + gx)*3;
                xv.x = p[0]; xv.y = p[1]; xv.z = p[2];
            }
            if (!FIRST) hv = hin[b*PIX + gy*WW + gx];
        }
        s_xt[ly][lx] = xv;
        if (!FIRST) s_ht[ly][lx] = hv;
    }
    __syncthreads();

    const int tx = tid & 31, ty = tid >> 5;

    float acc[16];
#pragma unroll
    for (int k = 0; k < 16; k++) acc[k] = s_bias[k];

    const int CIMAX = (CINSRC == 3) ? 3 : 4;

#pragma unroll
    for (int dy = 0; dy < 3; dy++) {
#pragma unroll
        for (int dx = 0; dx < 3; dx++) {
            const int tap = dy*3 + dx;
            {   // x-conv
                float4 v = s_xt[ty+dy][tx+dx];
                float vv[4] = {v.x, v.y, v.z, v.w};
#pragma unroll
                for (int ci = 0; ci < CIMAX; ci++) {
                    float val = vv[ci];
#pragma unroll
                    for (int j = 0; j < 4; j++) {
                        float4 wv = s_wx4[(tap*4 + ci)*4 + j];
                        acc[j*4+0] += val * wv.x;
                        acc[j*4+1] += val * wv.y;
                        acc[j*4+2] += val * wv.z;
                        acc[j*4+3] += val * wv.w;
                    }
                }
            }
            if (!FIRST) {  // h-conv
                float4 h = s_ht[ty+dy][tx+dx];
                float hv[4] = {h.x, h.y, h.z, h.w};
#pragma unroll
                for (int ci = 0; ci < 4; ci++) {
                    float val = hv[ci];
#pragma unroll
                    for (int j = 0; j < 4; j++) {
                        float4 wv = s_wh4[(tap*4 + ci)*4 + j];
                        acc[j*4+0] += val * wv.x;
                        acc[j*4+1] += val * wv.y;
                        acc[j*4+2] += val * wv.z;
                        acc[j*4+3] += val * wv.w;
                    }
                }
            }
        }
    }

    const int pix  = (ty0+ty)*WW + (tx0+tx);
    const int sidx = b*PIX + pix;

    float cold[4] = {0.f, 0.f, 0.f, 0.f};
    if (!FIRST) {
        float4 t = g_cS[sidx];
        cold[0]=t.x; cold[1]=t.y; cold[2]=t.z; cold[3]=t.w;
    }

    float cn[4], hn[4];
#pragma unroll
    for (int c = 0; c < 4; c++) {
        float iv = sigf(acc[c]);
        float fv = sigf(acc[4+c]);
        float gv = tanhfast(acc[8+c]);
        float ov = sigf(acc[12+c]);
        float cc = fv*cold[c] + iv*gv;
        cn[c] = cc;
        hn[c] = ov * tanhfast(cc);
    }
    g_cS[sidx] = make_float4(cn[0], cn[1], cn[2], cn[3]);
    hout[sidx] = make_float4(hn[0], hn[1], hn[2], hn[3]);

    if (MODE != 0) {
        float o[4];
#pragma unroll
        for (int c = 0; c < 4; c++) {
            float v = s_scale[c]*hn[c] + s_shift[c];
            if (MODE == 2) v = lreluf(v);
            o[c] = v;
        }
        seq_out[(long)b*s_pxb + pix] = make_float4(o[0], o[1], o[2], o[3]);
    }
}

// ---------------------------------------------------------------------------
// dense1: (64 x 65536) @ (65536 x 128) — split-K partials (deterministic)
// ---------------------------------------------------------------------------
__global__ __launch_bounds__(256)
void gemm1_part(const float* __restrict__ A, const float* __restrict__ Wm,
                float* __restrict__ part)
{
    __shared__ __align__(16) float xs[64][32];
    __shared__ __align__(16) float ws[32][128];

    const int tid   = threadIdx.x;
    const int s     = blockIdx.x;
    const int kbase = s * KS;
    const int r0    = (tid >> 5) * 8;   // 8 warps -> 8 row groups of 8
    const int c0    = (tid & 31) * 4;   // 32 lanes -> 128 cols in float4

    float acc[8][4];
#pragma unroll
    for (int i = 0; i < 8; i++)
#pragma unroll
        for (int j = 0; j < 4; j++) acc[i][j] = 0.f;

    for (int ch = 0; ch < KS/32; ch++) {
        const int k0 = kbase + ch*32;
        for (int i = tid; i < 64*32; i += 256) {
            int r = i >> 5, kk = i & 31;
            xs[r][kk] = A[(long)r*65536 + k0 + kk];
        }
        for (int i = tid; i < 32*128; i += 256) {
            int kk = i >> 7, n = i & 127;
            ws[kk][n] = Wm[(long)(k0 + kk)*128 + n];
        }
        __syncthreads();
#pragma unroll
        for (int kk = 0; kk < 32; kk++) {
            float4 wv = *reinterpret_cast<const float4*>(&ws[kk][c0]);
#pragma unroll
            for (int i = 0; i < 8; i++) {
                float a = xs[r0+i][kk];
                acc[i][0] += a*wv.x; acc[i][1] += a*wv.y;
                acc[i][2] += a*wv.z; acc[i][3] += a*wv.w;
            }
        }
        __syncthreads();
    }

    float* pout = part + (long)s*8192;
#pragma unroll
    for (int i = 0; i < 8; i++)
#pragma unroll
        for (int j = 0; j < 4; j++)
            pout[(r0+i)*128 + c0 + j] = acc[i][j];
}

__global__ void reduce1(const float* __restrict__ part, const float* __restrict__ bias,
                        float* __restrict__ out)
{
    int idx = blockIdx.x*256 + threadIdx.x;   // 0..8191  (r*128 + c)
    float a = bias[idx & 127];
    for (int s = 0; s < NSPLIT; s++) a += part[s*8192 + idx];
    out[idx] = lreluf(a);
}

// small dense: (64 x 128) @ (128 x N), optional leaky relu
__global__ void dense_small(const float* __restrict__ xin, const float* __restrict__ w,
                            const float* __restrict__ bias, float* __restrict__ out,
                            int N, int relu)
{
    __shared__ float xs[128];
    const int b = blockIdx.x;
    xs[threadIdx.x] = xin[b*128 + threadIdx.x];
    __syncthreads();
    const int n = threadIdx.x;
    if (n < N) {
        float a = bias[n];
#pragma unroll 8
        for (int k = 0; k < 128; k++) a += xs[k] * w[k*N + n];
        if (relu) a = lreluf(a);
        out[b*N + n] = a;
    }
}

// ---------------------------------------------------------------------------
// Launch
// ---------------------------------------------------------------------------
extern "C" void kernel_launch(void* const* d_in, const int* in_sizes, int n_in,
                              void* d_out, int out_size)
{
    const float* x    = (const float*)d_in[0];
    const float* wx1  = (const float*)d_in[1];
    const float* wh1  = (const float*)d_in[2];
    const float* b1   = (const float*)d_in[3];
    const float* g1   = (const float*)d_in[4];
    const float* bt1  = (const float*)d_in[5];
    const float* m1   = (const float*)d_in[6];
    const float* v1   = (const float*)d_in[7];
    const float* wx2  = (const float*)d_in[8];
    const float* wh2  = (const float*)d_in[9];
    const float* b2   = (const float*)d_in[10];
    const float* g2   = (const float*)d_in[11];
    const float* bt2  = (const float*)d_in[12];
    const float* m2   = (const float*)d_in[13];
    const float* v2   = (const float*)d_in[14];
    const float* wx3  = (const float*)d_in[15];
    const float* wh3  = (const float*)d_in[16];
    const float* b3   = (const float*)d_in[17];
    const float* g3   = (const float*)d_in[18];
    const float* bt3  = (const float*)d_in[19];
    const float* m3   = (const float*)d_in[20];
    const float* v3   = (const float*)d_in[21];
    const float* w_d1 = (const float*)d_in[22];
    const float* b_d1 = (const float*)d_in[23];
    const float* w_d2 = (const float*)d_in[24];
    const float* b_d2 = (const float*)d_in[25];
    const float* w_d3 = (const float*)d_in[26];
    const float* b_d3 = (const float*)d_in[27];
    const float* w_o  = (const float*)d_in[28];
    const float* b_o  = (const float*)d_in[29];

    float4 *seqA, *seqB, *hA, *hB, *hbn;
    float  *part, *d1, *d2, *d3;
    cudaGetSymbolAddress((void**)&seqA, g_seqA);
    cudaGetSymbolAddress((void**)&seqB, g_seqB);
    cudaGetSymbolAddress((void**)&hA,   g_hA);
    cudaGetSymbolAddress((void**)&hB,   g_hB);
    cudaGetSymbolAddress((void**)&hbn,  g_hbn);
    cudaGetSymbolAddress((void**)&part, g_part);
    cudaGetSymbolAddress((void**)&d1,   g_d1);
    cudaGetSymbolAddress((void**)&d2,   g_d2);
    cudaGetSymbolAddress((void**)&d3,   g_d3);

    dim3 grid(WW/TW, HH/TH, BB);

    // ---- layer 1 (Cin=3): x -> seqA (BN applied on write) ----
    lstm_step<3,true ,1><<<grid,256>>>(x, TT*PIX, wx1, wh1, b1, g1,bt1,m1,v1,
                                       nullptr, hB, seqA, TT*PIX);
    for (int t = 1; t < TT; t++) {
        const float4* hin  = (t & 1) ? hB : hA;
        float4*       hout = (t & 1) ? hA : hB;
        lstm_step<3,false,1><<<grid,256>>>(x + (long)t*PIX*3, TT*PIX, wx1, wh1, b1,
                                           g1,bt1,m1,v1, hin, hout,
                                           seqA + (long)t*PIX, TT*PIX);
    }

    // ---- layer 2 (Cin=4): seqA -> seqB ----
    lstm_step<4,true ,1><<<grid,256>>>((const float*)seqA, TT*PIX, wx2, wh2, b2,
                                       g2,bt2,m2,v2, nullptr, hB, seqB, TT*PIX);
    for (int t = 1; t < TT; t++) {
        const float4* hin  = (t & 1) ? hB : hA;
        float4*       hout = (t & 1) ? hA : hB;
        lstm_step<4,false,1><<<grid,256>>>((const float*)(seqB /*dummy*/, seqA + (long)t*PIX),
                                           TT*PIX, wx2, wh2, b2, g2,bt2,m2,v2,
                                           hin, hout, seqB + (long)t*PIX, TT*PIX);
    }

    // ---- layer 3 (Cin=4): seqB -> hbn (only final h, BN + leaky relu) ----
    lstm_step<4,true ,0><<<grid,256>>>((const float*)seqB, TT*PIX, wx3, wh3, b3,
                                       g3,bt3,m3,v3, nullptr, hB, nullptr, 0);
    for (int t = 1; t < TT-1; t++) {
        const float4* hin  = (t & 1) ? hB : hA;
        float4*       hout = (t & 1) ? hA : hB;
        lstm_step<4,false,0><<<grid,256>>>((const float*)(seqB + (long)t*PIX), TT*PIX,
                                           wx3, wh3, b3, g3,bt3,m3,v3,
                                           hin, hout, nullptr, 0);
    }
    {
        const int t = TT-1;  // t = 4: read hA (t&1==0), write hB, emit BN+lrelu
        lstm_step<4,false,2><<<grid,256>>>((const float*)(seqB + (long)t*PIX), TT*PIX,
                                           wx3, wh3, b3, g3,bt3,m3,v3,
                                           hA, hB, hbn, PIX);
    }

    // ---- dense head ----
    gemm1_part<<<NSPLIT,256>>>((const float*)hbn, w_d1, part);
    reduce1<<<32,256>>>(part, b_d1, d1);
    dense_small<<<BB,128>>>(d1, w_d2, b_d2, d2, 128, 1);
    dense_small<<<BB,128>>>(d2, w_d3, b_d3, d3, 128, 1);
    dense_small<<<BB,128>>>(d3, w_o,  b_o,  (float*)d_out, 2, 0);
}

// round 2
// speedup vs baseline: 1.0185x; 1.0185x over previous
#include <cuda_runtime.h>
#include <math.h>

// ---------------------------------------------------------------------------
// Problem constants
// ---------------------------------------------------------------------------
#define HH   128
#define WW   128
#define BB   64
#define TT   5
#define PIX  (HH*WW)        // 16384 pixels per image

// lstm tile: block = 128 threads (32 x 4), each thread computes a 4-pixel
// vertical strip -> tile = 32 wide x 16 tall
#define TW   32
#define THY  4
#define PPT  4
#define TILH (THY*PPT)      // 16

#define NSPLIT 256          // split-K slices for dense1
#define KS     256          // K per slice (256*256 = 65536)

// ---------------------------------------------------------------------------
// Static device scratch (no allocations allowed)
// ---------------------------------------------------------------------------
__device__ float4 g_seqA[BB*TT*PIX];    // layer1 output (BN applied), (B,T,H,W,4)
__device__ float4 g_seqB[BB*TT*PIX];    // layer2 output (BN applied)
__device__ float4 g_hA[BB*PIX];         // recurrent h double-buffer
__device__ float4 g_hB[BB*PIX];
__device__ float4 g_cS[BB*PIX];         // cell state (in-place safe: own-pixel only)
__device__ float4 g_hbn[BB*PIX];        // lrelu(bn(h_last))  == flattened (B,65536)
__device__ float  g_part[NSPLIT*BB*128];// dense1 split-K partials
__device__ float  g_d1[BB*128];
__device__ float  g_d2[BB*128];
__device__ float  g_d3[BB*128];

// ---------------------------------------------------------------------------
// Fast activations (abs err ~1e-7 — far below the 1e-3 gate)
// ---------------------------------------------------------------------------
__device__ __forceinline__ float sigf(float x) {
    return __fdividef(1.0f, 1.0f + __expf(-x));
}
__device__ __forceinline__ float tanhfast(float x) {
    float e = __expf(-2.0f * fabsf(x));
    float r = __fdividef(1.0f - e, 1.0f + e);
    return copysignf(r, x);
}
__device__ __forceinline__ float lreluf(float x) { return x > 0.0f ? x : 0.3f * x; }

__device__ __forceinline__ float getc(float4 v, int ci) {
    return (ci == 0) ? v.x : (ci == 1) ? v.y : (ci == 2) ? v.z : v.w;
}

// ---------------------------------------------------------------------------
// One ConvLSTM2D timestep (fused: x-conv + h-conv + gates + state + BN write)
//   CINSRC : input channels of x (3 for layer1, 4 for layers 2/3)
//   FIRST  : t==0 -> h=c=0, skip h-conv and state reads
//   MODE   : 0 = no seq write, 1 = write bn(h) to seq_out, 2 = write lrelu(bn(h))
// Each thread owns a 4-pixel vertical strip; weights are fetched from SMEM
// once per (tap, ci) and applied to all 4 pixels (amortizes LDS 4x vs R1).
// ---------------------------------------------------------------------------
template<int CINSRC, bool FIRST, int MODE>
__global__ __launch_bounds__(128)
void lstm_step(const float* __restrict__ xin, int x_pxb,
               const float* __restrict__ wx, const float* __restrict__ wh,
               const float* __restrict__ bias,
               const float* __restrict__ bng, const float* __restrict__ bnb,
               const float* __restrict__ bnm, const float* __restrict__ bnv,
               const float4* __restrict__ hin, float4* __restrict__ hout,
               float4* __restrict__ seq_out, int s_pxb)
{
    __shared__ float4 s_wx4[144];            // [tap][ci(4, zero-padded)][j(4)] -> 16 couts
    __shared__ float4 s_wh4[144];
    __shared__ float  s_bias[16];
    __shared__ float  s_scale[4], s_shift[4];
    __shared__ float4 s_xt[TILH+2][TW+2];    // 18 x 34
    __shared__ float4 s_ht[TILH+2][TW+2];

    const int tid = threadIdx.x;
    const int b   = blockIdx.z;
    const int ty0 = blockIdx.y * TILH;
    const int tx0 = blockIdx.x * TW;

    // ---- stage weights ----
    {
        float* s_wxf = (float*)s_wx4;
        for (int i = tid; i < 576; i += 128) {
            int tap = i >> 6, r = i & 63, ci = r >> 4, co = r & 15;
            s_wxf[i] = (ci < CINSRC) ? wx[(tap*CINSRC + ci)*16 + co] : 0.0f;
        }
        if (!FIRST) {
            float* s_whf = (float*)s_wh4;
            for (int i = tid; i < 576; i += 128) s_whf[i] = wh[i];
        }
        if (tid < 16) s_bias[tid] = bias[tid];
        if (MODE != 0 && tid < 4) {
            float sc = bng[tid] * rsqrtf(bnv[tid] + 1e-3f);
            s_scale[tid] = sc;
            s_shift[tid] = bnb[tid] - bnm[tid]*sc;
        }
    }

    // ---- stage x / h tiles with halo (zero padded) ----
    const float4* x4 = reinterpret_cast<const float4*>(xin);
    for (int i = tid; i < (TILH+2)*(TW+2); i += 128) {
        int ly = i / (TW+2), lx = i % (TW+2);
        int gy = ty0 + ly - 1, gx = tx0 + lx - 1;
        bool ok = (gy >= 0) && (gy < HH) && (gx >= 0) && (gx < WW);
        float4 xv = make_float4(0.f,0.f,0.f,0.f);
        float4 hv = make_float4(0.f,0.f,0.f,0.f);
        if (ok) {
            if (CINSRC == 4) {
                xv = x4[(long)b*x_pxb + gy*WW + gx];
            } else {
                const float* p = xin + ((long)b*x_pxb + gy*WW + gx)*3;
                xv.x = p[0]; xv.y = p[1]; xv.z = p[2];
            }
            if (!FIRST) hv = hin[b*PIX + gy*WW + gx];
        }
        s_xt[ly][lx] = xv;
        if (!FIRST) s_ht[ly][lx] = hv;
    }
    __syncthreads();

    const int tx = tid & 31;        // 0..31
    const int ty = tid >> 5;        // 0..3
    const int ry = ty * PPT;        // base row in tile

    float acc[PPT][16];
#pragma unroll
    for (int p = 0; p < PPT; p++)
#pragma unroll
        for (int k = 0; k < 16; k++) acc[p][k] = s_bias[k];

    const int CIMAX = (CINSRC == 3) ? 3 : 4;

    // ---- x conv ----
#pragma unroll
    for (int dx = 0; dx < 3; dx++) {
        float4 colv[PPT+2];
#pragma unroll
        for (int r = 0; r < PPT+2; r++) colv[r] = s_xt[ry + r][tx + dx];
#pragma unroll
        for (int dy = 0; dy < 3; dy++) {
            const int tap = dy*3 + dx;
#pragma unroll
            for (int ci = 0; ci < CIMAX; ci++) {
                float4 w0 = s_wx4[(tap*4 + ci)*4 + 0];
                float4 w1 = s_wx4[(tap*4 + ci)*4 + 1];
                float4 w2 = s_wx4[(tap*4 + ci)*4 + 2];
                float4 w3 = s_wx4[(tap*4 + ci)*4 + 3];
#pragma unroll
                for (int p = 0; p < PPT; p++) {
                    float val = getc(colv[dy + p], ci);
                    acc[p][ 0] += val*w0.x; acc[p][ 1] += val*w0.y;
                    acc[p][ 2] += val*w0.z; acc[p][ 3] += val*w0.w;
                    acc[p][ 4] += val*w1.x; acc[p][ 5] += val*w1.y;
                    acc[p][ 6] += val*w1.z; acc[p][ 7] += val*w1.w;
                    acc[p][ 8] += val*w2.x; acc[p][ 9] += val*w2.y;
                    acc[p][10] += val*w2.z; acc[p][11] += val*w2.w;
                    acc[p][12] += val*w3.x; acc[p][13] += val*w3.y;
                    acc[p][14] += val*w3.z; acc[p][15] += val*w3.w;
                }
            }
        }
    }

    // ---- h conv ----
    if (!FIRST) {
#pragma unroll
        for (int dx = 0; dx < 3; dx++) {
            float4 colv[PPT+2];
#pragma unroll
            for (int r = 0; r < PPT+2; r++) colv[r] = s_ht[ry + r][tx + dx];
#pragma unroll
            for (int dy = 0; dy < 3; dy++) {
                const int tap = dy*3 + dx;
#pragma unroll
                for (int ci = 0; ci < 4; ci++) {
                    float4 w0 = s_wh4[(tap*4 + ci)*4 + 0];
                    float4 w1 = s_wh4[(tap*4 + ci)*4 + 1];
                    float4 w2 = s_wh4[(tap*4 + ci)*4 + 2];
                    float4 w3 = s_wh4[(tap*4 + ci)*4 + 3];
#pragma unroll
                    for (int p = 0; p < PPT; p++) {
                        float val = getc(colv[dy + p], ci);
                        acc[p][ 0] += val*w0.x; acc[p][ 1] += val*w0.y;
                        acc[p][ 2] += val*w0.z; acc[p][ 3] += val*w0.w;
                        acc[p][ 4] += val*w1.x; acc[p][ 5] += val*w1.y;
                        acc[p][ 6] += val*w1.z; acc[p][ 7] += val*w1.w;
                        acc[p][ 8] += val*w2.x; acc[p][ 9] += val*w2.y;
                        acc[p][10] += val*w2.z; acc[p][11] += val*w2.w;
                        acc[p][12] += val*w3.x; acc[p][13] += val*w3.y;
                        acc[p][14] += val*w3.z; acc[p][15] += val*w3.w;
                    }
                }
            }
        }
    }

    // ---- gates + state + optional BN seq write, per strip pixel ----
#pragma unroll
    for (int p = 0; p < PPT; p++) {
        const int pix  = (ty0 + ry + p)*WW + (tx0 + tx);
        const int sidx = b*PIX + pix;

        float cold[4] = {0.f, 0.f, 0.f, 0.f};
        if (!FIRST) {
            float4 t = g_cS[sidx];
            cold[0]=t.x; cold[1]=t.y; cold[2]=t.z; cold[3]=t.w;
        }

        float cn[4], hn[4];
#pragma unroll
        for (int c = 0; c < 4; c++) {
            float iv = sigf(acc[p][c]);
            float fv = sigf(acc[p][4+c]);
            float gv = tanhfast(acc[p][8+c]);
            float ov = sigf(acc[p][12+c]);
            float cc = fv*cold[c] + iv*gv;
            cn[c] = cc;
            hn[c] = ov * tanhfast(cc);
        }
        g_cS[sidx] = make_float4(cn[0], cn[1], cn[2], cn[3]);
        hout[sidx] = make_float4(hn[0], hn[1], hn[2], hn[3]);

        if (MODE != 0) {
            float o[4];
#pragma unroll
            for (int c = 0; c < 4; c++) {
                float v = s_scale[c]*hn[c] + s_shift[c];
                if (MODE == 2) v = lreluf(v);
                o[c] = v;
            }
            seq_out[(long)b*s_pxb + pix] = make_float4(o[0], o[1], o[2], o[3]);
        }
    }
}

// ---------------------------------------------------------------------------
// dense1: (64 x 65536) @ (65536 x 128) — split-K partials (deterministic)
// ---------------------------------------------------------------------------
__global__ __launch_bounds__(256)
void gemm1_part(const float* __restrict__ A, const float* __restrict__ Wm,
                float* __restrict__ part)
{
    __shared__ __align__(16) float xs[64][32];
    __shared__ __align__(16) float ws[32][128];

    const int tid   = threadIdx.x;
    const int s     = blockIdx.x;
    const int kbase = s * KS;
    const int r0    = (tid >> 5) * 8;   // 8 warps -> 8 row groups of 8
    const int c0    = (tid & 31) * 4;   // 32 lanes -> 128 cols in float4

    float acc[8][4];
#pragma unroll
    for (int i = 0; i < 8; i++)
#pragma unroll
        for (int j = 0; j < 4; j++) acc[i][j] = 0.f;

    for (int ch = 0; ch < KS/32; ch++) {
        const int k0 = kbase + ch*32;
        for (int i = tid; i < 64*32; i += 256) {
            int r = i >> 5, kk = i & 31;
            xs[r][kk] = A[(long)r*65536 + k0 + kk];
        }
        for (int i = tid; i < 32*128; i += 256) {
            int kk = i >> 7, n = i & 127;
            ws[kk][n] = Wm[(long)(k0 + kk)*128 + n];
        }
        __syncthreads();
#pragma unroll
        for (int kk = 0; kk < 32; kk++) {
            float4 wv = *reinterpret_cast<const float4*>(&ws[kk][c0]);
#pragma unroll
            for (int i = 0; i < 8; i++) {
                float a = xs[r0+i][kk];
                acc[i][0] += a*wv.x; acc[i][1] += a*wv.y;
                acc[i][2] += a*wv.z; acc[i][3] += a*wv.w;
            }
        }
        __syncthreads();
    }

    float* pout = part + (long)s*8192;
#pragma unroll
    for (int i = 0; i < 8; i++)
#pragma unroll
        for (int j = 0; j < 4; j++)
            pout[(r0+i)*128 + c0 + j] = acc[i][j];
}

__global__ void reduce1(const float* __restrict__ part, const float* __restrict__ bias,
                        float* __restrict__ out)
{
    int idx = blockIdx.x*256 + threadIdx.x;   // 0..8191  (r*128 + c)
    float a = bias[idx & 127];
    for (int s = 0; s < NSPLIT; s++) a += part[s*8192 + idx];
    out[idx] = lreluf(a);
}

// small dense: (64 x 128) @ (128 x N), optional leaky relu
__global__ void dense_small(const float* __restrict__ xin, const float* __restrict__ w,
                            const float* __restrict__ bias, float* __restrict__ out,
                            int N, int relu)
{
    __shared__ float xs[128];
    const int b = blockIdx.x;
    xs[threadIdx.x] = xin[b*128 + threadIdx.x];
    __syncthreads();
    const int n = threadIdx.x;
    if (n < N) {
        float a = bias[n];
#pragma unroll 8
        for (int k = 0; k < 128; k++) a += xs[k] * w[k*N + n];
        if (relu) a = lreluf(a);
        out[b*N + n] = a;
    }
}

// ---------------------------------------------------------------------------
// Launch
// ---------------------------------------------------------------------------
extern "C" void kernel_launch(void* const* d_in, const int* in_sizes, int n_in,
                              void* d_out, int out_size)
{
    const float* x    = (const float*)d_in[0];
    const float* wx1  = (const float*)d_in[1];
    const float* wh1  = (const float*)d_in[2];
    const float* b1   = (const float*)d_in[3];
    const float* g1   = (const float*)d_in[4];
    const float* bt1  = (const float*)d_in[5];
    const float* m1   = (const float*)d_in[6];
    const float* v1   = (const float*)d_in[7];
    const float* wx2  = (const float*)d_in[8];
    const float* wh2  = (const float*)d_in[9];
    const float* b2   = (const float*)d_in[10];
    const float* g2   = (const float*)d_in[11];
    const float* bt2  = (const float*)d_in[12];
    const float* m2   = (const float*)d_in[13];
    const float* v2   = (const float*)d_in[14];
    const float* wx3  = (const float*)d_in[15];
    const float* wh3  = (const float*)d_in[16];
    const float* b3   = (const float*)d_in[17];
    const float* g3   = (const float*)d_in[18];
    const float* bt3  = (const float*)d_in[19];
    const float* m3   = (const float*)d_in[20];
    const float* v3   = (const float*)d_in[21];
    const float* w_d1 = (const float*)d_in[22];
    const float* b_d1 = (const float*)d_in[23];
    const float* w_d2 = (const float*)d_in[24];
    const float* b_d2 = (const float*)d_in[25];
    const float* w_d3 = (const float*)d_in[26];
    const float* b_d3 = (const float*)d_in[27];
    const float* w_o  = (const float*)d_in[28];
    const float* b_o  = (const float*)d_in[29];

    float4 *seqA, *seqB, *hA, *hB, *hbn;
    float  *part, *d1, *d2, *d3;
    cudaGetSymbolAddress((void**)&seqA, g_seqA);
    cudaGetSymbolAddress((void**)&seqB, g_seqB);
    cudaGetSymbolAddress((void**)&hA,   g_hA);
    cudaGetSymbolAddress((void**)&hB,   g_hB);
    cudaGetSymbolAddress((void**)&hbn,  g_hbn);
    cudaGetSymbolAddress((void**)&part, g_part);
    cudaGetSymbolAddress((void**)&d1,   g_d1);
    cudaGetSymbolAddress((void**)&d2,   g_d2);
    cudaGetSymbolAddress((void**)&d3,   g_d3);

    dim3 grid(WW/TW, HH/TILH, BB);   // (4, 8, 64)

    // ---- layer 1 (Cin=3): x -> seqA (BN applied on write) ----
    lstm_step<3,true ,1><<<grid,128>>>(x, TT*PIX, wx1, wh1, b1, g1,bt1,m1,v1,
                                       nullptr, hB, seqA, TT*PIX);
    for (int t = 1; t < TT; t++) {
        const float4* hin  = (t & 1) ? hB : hA;
        float4*       hout = (t & 1) ? hA : hB;
        lstm_step<3,false,1><<<grid,128>>>(x + (long)t*PIX*3, TT*PIX, wx1, wh1, b1,
                                           g1,bt1,m1,v1, hin, hout,
                                           seqA + (long)t*PIX, TT*PIX);
    }

    // ---- layer 2 (Cin=4): seqA -> seqB ----
    lstm_step<4,true ,1><<<grid,128>>>((const float*)seqA, TT*PIX, wx2, wh2, b2,
                                       g2,bt2,m2,v2, nullptr, hB, seqB, TT*PIX);
    for (int t = 1; t < TT; t++) {
        const float4* hin  = (t & 1) ? hB : hA;
        float4*       hout = (t & 1) ? hA : hB;
        lstm_step<4,false,1><<<grid,128>>>((const float*)(seqA + (long)t*PIX), TT*PIX,
                                           wx2, wh2, b2, g2,bt2,m2,v2,
                                           hin, hout, seqB + (long)t*PIX, TT*PIX);
    }

    // ---- layer 3 (Cin=4): seqB -> hbn (only final h, BN + leaky relu) ----
    lstm_step<4,true ,0><<<grid,128>>>((const float*)seqB, TT*PIX, wx3, wh3, b3,
                                       g3,bt3,m3,v3, nullptr, hB, nullptr, 0);
    for (int t = 1; t < TT-1; t++) {
        const float4* hin  = (t & 1) ? hB : hA;
        float4*       hout = (t & 1) ? hA : hB;
        lstm_step<4,false,0><<<grid,128>>>((const float*)(seqB + (long)t*PIX), TT*PIX,
                                           wx3, wh3, b3, g3,bt3,m3,v3,
                                           hin, hout, nullptr, 0);
    }
    {
        const int t = TT-1;  // t = 4: read hA (t&1==0), write hB, emit BN+lrelu
        lstm_step<4,false,2><<<grid,128>>>((const float*)(seqB + (long)t*PIX), TT*PIX,
                                           wx3, wh3, b3, g3,bt3,m3,v3,
                                           hA, hB, hbn, PIX);
    }

    // ---- dense head ----
    gemm1_part<<<NSPLIT,256>>>((const float*)hbn, w_d1, part);
    reduce1<<<32,256>>>(part, b_d1, d1);
    dense_small<<<BB,128>>>(d1, w_d2, b_d2, d2, 128, 1);
    dense_small<<<BB,128>>>(d2, w_d3, b_d3, d3, 128, 1);
    dense_small<<<BB,128>>>(d3, w_o,  b_o,  (float*)d_out, 2, 0);
}

// round 4
// speedup vs baseline: 1.3027x; 1.2790x over previous
#include <cuda_runtime.h>
#include <math.h>
#include <stdint.h>

// ---------------------------------------------------------------------------
// Problem constants
// ---------------------------------------------------------------------------
#define HH   128
#define WW   128
#define BB   64
#define TT   5
#define PIX  (HH*WW)        // 16384 pixels per image

// lstm tile: block = 128 threads (32 x 4), each thread computes a 4-pixel
// vertical strip -> tile = 32 wide x 16 tall
#define TW   32
#define THY  4
#define PPT  4
#define TILH (THY*PPT)      // 16

#define NSPLIT 256          // split-K slices for dense1
#define KS     256          // K per slice (256*256 = 65536)

// ---------------------------------------------------------------------------
// Static device scratch (no allocations allowed)
// ---------------------------------------------------------------------------
__device__ float4 g_seqA[BB*TT*PIX];    // layer1 output (BN applied), (B,T,H,W,4)
__device__ float4 g_seqB[BB*TT*PIX];    // layer2 output (BN applied)
__device__ float4 g_hA[BB*PIX];         // recurrent h double-buffer
__device__ float4 g_hB[BB*PIX];
__device__ float4 g_cS[BB*PIX];         // cell state (in-place safe: own-pixel only)
__device__ float4 g_hbn[BB*PIX];        // lrelu(bn(h_last))  == flattened (B,65536)
__device__ float  g_part[NSPLIT*BB*128];// dense1 split-K partials
__device__ float  g_d1[BB*128];
__device__ float  g_d2[BB*128];
__device__ float  g_d3[BB*128];

// ---------------------------------------------------------------------------
// Packed f32x2 helpers (Blackwell packed fp32 FMA — ptxas never emits these
// from plain C++, only via explicit PTX)
// ---------------------------------------------------------------------------
__device__ __forceinline__ uint64_t pack2(float lo, float hi) {
    uint64_t r;
    asm("mov.b64 %0, {%1, %2};" : "=l"(r) : "f"(lo), "f"(hi));
    return r;
}
__device__ __forceinline__ void fma2(uint64_t& d, uint64_t a, uint64_t b) {
    asm("fma.rn.f32x2 %0, %1, %2, %0;" : "+l"(d) : "l"(a), "l"(b));
}
__device__ __forceinline__ float2 unpack2(uint64_t v) {
    float2 r;
    asm("mov.b64 {%0, %1}, %2;" : "=f"(r.x), "=f"(r.y) : "l"(v));
    return r;
}

// ---------------------------------------------------------------------------
// Fast activations (abs err ~1e-7 — far below the 1e-3 gate).
// NOTE: deliberately NOT tanh.approx (5e-4 abs err would risk the gate
// through the 5-step recurrence).
// ---------------------------------------------------------------------------
__device__ __forceinline__ float sigf(float x) {
    return __fdividef(1.0f, 1.0f + __expf(-x));
}
__device__ __forceinline__ float tanhfast(float x) {
    float e = __expf(-2.0f * fabsf(x));
    float r = __fdividef(1.0f - e, 1.0f + e);
    return copysignf(r, x);
}
__device__ __forceinline__ float lreluf(float x) { return x > 0.0f ? x : 0.3f * x; }

__device__ __forceinline__ float getc(float4 v, int ci) {
    return (ci == 0) ? v.x : (ci == 1) ? v.y : (ci == 2) ? v.z : v.w;
}

// ---------------------------------------------------------------------------
// One ConvLSTM2D timestep (fused: x-conv + h-conv + gates + state + BN write)
//   CINSRC : input channels of x (3 for layer1, 4 for layers 2/3)
//   FIRST  : t==0 -> h=c=0, skip h-conv and state reads
//   MODE   : 0 = no seq write, 1 = write bn(h) to seq_out, 2 = write lrelu(bn(h))
// Each thread owns a 4-pixel vertical strip. The 16 gate accumulators are
// held as 8 f32x2 pairs; each (tap,ci) contribution = 1 mov.b64 broadcast +
// 8 fma.rn.f32x2 (instead of 16 FFMA).
// ---------------------------------------------------------------------------
template<int CINSRC, bool FIRST, int MODE>
__global__ __launch_bounds__(128)
void lstm_step(const float* __restrict__ xin, int x_pxb,
               const float* __restrict__ wx, const float* __restrict__ wh,
               const float* __restrict__ bias,
               const float* __restrict__ bng, const float* __restrict__ bnb,
               const float* __restrict__ bnm, const float* __restrict__ bnv,
               const float4* __restrict__ hin, float4* __restrict__ hout,
               float4* __restrict__ seq_out, int s_pxb)
{
    __shared__ float4 s_wx4[144];            // [tap][ci(4, zero-padded)][j(4)] -> 16 couts
    __shared__ float4 s_wh4[144];
    __shared__ float  s_bias[16];
    __shared__ float  s_scale[4], s_shift[4];
    __shared__ float4 s_xt[TILH+2][TW+2];    // 18 x 34
    __shared__ float4 s_ht[TILH+2][TW+2];

    const int tid = threadIdx.x;
    const int b   = blockIdx.z;
    const int ty0 = blockIdx.y * TILH;
    const int tx0 = blockIdx.x * TW;

    // ---- stage weights ----
    {
        float* s_wxf = (float*)s_wx4;
        for (int i = tid; i < 576; i += 128) {
            int tap = i >> 6, r = i & 63, ci = r >> 4, co = r & 15;
            s_wxf[i] = (ci < CINSRC) ? wx[(tap*CINSRC + ci)*16 + co] : 0.0f;
        }
        if (!FIRST) {
            float* s_whf = (float*)s_wh4;
            for (int i = tid; i < 576; i += 128) s_whf[i] = wh[i];
        }
        if (tid < 16) s_bias[tid] = bias[tid];
        if (MODE != 0 && tid < 4) {
            float sc = bng[tid] * rsqrtf(bnv[tid] + 1e-3f);
            s_scale[tid] = sc;
            s_shift[tid] = bnb[tid] - bnm[tid]*sc;
        }
    }

    // ---- stage x / h tiles with halo (zero padded) ----
    const float4* x4 = reinterpret_cast<const float4*>(xin);
    for (int i = tid; i < (TILH+2)*(TW+2); i += 128) {
        int ly = i / (TW+2), lx = i % (TW+2);
        int gy = ty0 + ly - 1, gx = tx0 + lx - 1;
        bool ok = (gy >= 0) && (gy < HH) && (gx >= 0) && (gx < WW);
        float4 xv = make_float4(0.f,0.f,0.f,0.f);
        float4 hv = make_float4(0.f,0.f,0.f,0.f);
        if (ok) {
            if (CINSRC == 4) {
                xv = x4[(long)b*x_pxb + gy*WW + gx];
            } else {
                const float* p = xin + ((long)b*x_pxb + gy*WW + gx)*3;
                xv.x = p[0]; xv.y = p[1]; xv.z = p[2];
            }
            if (!FIRST) hv = hin[b*PIX + gy*WW + gx];
        }
        s_xt[ly][lx] = xv;
        if (!FIRST) s_ht[ly][lx] = hv;
    }
    __syncthreads();

    const int tx = tid & 31;        // 0..31
    const int ty = tid >> 5;        // 0..3
    const int ry = ty * PPT;        // base row in tile

    // accumulators: acc2[p][j] holds couts (2j, 2j+1)
    uint64_t acc2[PPT][8];
    {
        uint64_t binit[8];
#pragma unroll
        for (int j = 0; j < 8; j++) binit[j] = pack2(s_bias[2*j], s_bias[2*j+1]);
#pragma unroll
        for (int p = 0; p < PPT; p++)
#pragma unroll
            for (int j = 0; j < 8; j++) acc2[p][j] = binit[j];
    }

    const int CIMAX = (CINSRC == 3) ? 3 : 4;

    // ---- x conv ----
#pragma unroll
    for (int dx = 0; dx < 3; dx++) {
        float4 colv[PPT+2];
#pragma unroll
        for (int r = 0; r < PPT+2; r++) colv[r] = s_xt[ry + r][tx + dx];
#pragma unroll
        for (int dy = 0; dy < 3; dy++) {
            const int tap = dy*3 + dx;
#pragma unroll
            for (int ci = 0; ci < CIMAX; ci++) {
                const ulonglong2* wp =
                    reinterpret_cast<const ulonglong2*>(&s_wx4[(tap*4 + ci)*4]);
                ulonglong2 wA = wp[0];   // couts 0..3  (two f32x2 pairs)
                ulonglong2 wB = wp[1];   // couts 4..7
                ulonglong2 wC = wp[2];   // couts 8..11
                ulonglong2 wD = wp[3];   // couts 12..15
#pragma unroll
                for (int p = 0; p < PPT; p++) {
                    float val = getc(colv[dy + p], ci);
                    uint64_t vv = pack2(val, val);
                    fma2(acc2[p][0], vv, wA.x); fma2(acc2[p][1], vv, wA.y);
                    fma2(acc2[p][2], vv, wB.x); fma2(acc2[p][3], vv, wB.y);
                    fma2(acc2[p][4], vv, wC.x); fma2(acc2[p][5], vv, wC.y);
                    fma2(acc2[p][6], vv, wD.x); fma2(acc2[p][7], vv, wD.y);
                }
            }
        }
    }

    // ---- h conv ----
    if (!FIRST) {
#pragma unroll
        for (int dx = 0; dx < 3; dx++) {
            float4 colv[PPT+2];
#pragma unroll
            for (int r = 0; r < PPT+2; r++) colv[r] = s_ht[ry + r][tx + dx];
#pragma unroll
            for (int dy = 0; dy < 3; dy++) {
                const int tap = dy*3 + dx;
#pragma unroll
                for (int ci = 0; ci < 4; ci++) {
                    const ulonglong2* wp =
                        reinterpret_cast<const ulonglong2*>(&s_wh4[(tap*4 + ci)*4]);
                    ulonglong2 wA = wp[0];
                    ulonglong2 wB = wp[1];
                    ulonglong2 wC = wp[2];
                    ulonglong2 wD = wp[3];
#pragma unroll
                    for (int p = 0; p < PPT; p++) {
                        float val = getc(colv[dy + p], ci);
                        uint64_t vv = pack2(val, val);
                        fma2(acc2[p][0], vv, wA.x); fma2(acc2[p][1], vv, wA.y);
                        fma2(acc2[p][2], vv, wB.x); fma2(acc2[p][3], vv, wB.y);
                        fma2(acc2[p][4], vv, wC.x); fma2(acc2[p][5], vv, wC.y);
                        fma2(acc2[p][6], vv, wD.x); fma2(acc2[p][7], vv, wD.y);
                    }
                }
            }
        }
    }

    // ---- gates + state + optional BN seq write, per strip pixel ----
#pragma unroll
    for (int p = 0; p < PPT; p++) {
        const int pix  = (ty0 + ry + p)*WW + (tx0 + tx);
        const int sidx = b*PIX + pix;

        float z[16];
#pragma unroll
        for (int j = 0; j < 8; j++) {
            float2 u = unpack2(acc2[p][j]);
            z[2*j]   = u.x;
            z[2*j+1] = u.y;
        }

        float cold[4] = {0.f, 0.f, 0.f, 0.f};
        if (!FIRST) {
            float4 t = g_cS[sidx];
            cold[0]=t.x; cold[1]=t.y; cold[2]=t.z; cold[3]=t.w;
        }

        float cn[4], hn[4];
#pragma unroll
        for (int c = 0; c < 4; c++) {
            float iv = sigf(z[c]);
            float fv = sigf(z[4+c]);
            float gv = tanhfast(z[8+c]);
            float ov = sigf(z[12+c]);
            float cc = fv*cold[c] + iv*gv;
            cn[c] = cc;
            hn[c] = ov * tanhfast(cc);
        }
        g_cS[sidx] = make_float4(cn[0], cn[1], cn[2], cn[3]);
        hout[sidx] = make_float4(hn[0], hn[1], hn[2], hn[3]);

        if (MODE != 0) {
            float o[4];
#pragma unroll
            for (int c = 0; c < 4; c++) {
                float v = s_scale[c]*hn[c] + s_shift[c];
                if (MODE == 2) v = lreluf(v);
                o[c] = v;
            }
            seq_out[(long)b*s_pxb + pix] = make_float4(o[0], o[1], o[2], o[3]);
        }
    }
}

// ---------------------------------------------------------------------------
// dense1: (64 x 65536) @ (65536 x 128) — split-K partials (deterministic)
// ---------------------------------------------------------------------------
__global__ __launch_bounds__(256)
void gemm1_part(const float* __restrict__ A, const float* __restrict__ Wm,
                float* __restrict__ part)
{
    __shared__ __align__(16) float xs[64][32];
    __shared__ __align__(16) float ws[32][128];

    const int tid   = threadIdx.x;
    const int s     = blockIdx.x;
    const int kbase = s * KS;
    const int r0    = (tid >> 5) * 8;   // 8 warps -> 8 row groups of 8
    const int c0    = (tid & 31) * 4;   // 32 lanes -> 128 cols in float4

    float acc[8][4];
#pragma unroll
    for (int i = 0; i < 8; i++)
#pragma unroll
        for (int j = 0; j < 4; j++) acc[i][j] = 0.f;

    for (int ch = 0; ch < KS/32; ch++) {
        const int k0 = kbase + ch*32;
        for (int i = tid; i < 64*32; i += 256) {
            int r = i >> 5, kk = i & 31;
            xs[r][kk] = A[(long)r*65536 + k0 + kk];
        }
        for (int i = tid; i < 32*128; i += 256) {
            int kk = i >> 7, n = i & 127;
            ws[kk][n] = Wm[(long)(k0 + kk)*128 + n];
        }
        __syncthreads();
#pragma unroll
        for (int kk = 0; kk < 32; kk++) {
            float4 wv = *reinterpret_cast<const float4*>(&ws[kk][c0]);
#pragma unroll
            for (int i = 0; i < 8; i++) {
                float a = xs[r0+i][kk];
                acc[i][0] += a*wv.x; acc[i][1] += a*wv.y;
                acc[i][2] += a*wv.z; acc[i][3] += a*wv.w;
            }
        }
        __syncthreads();
    }

    float* pout = part + (long)s*8192;
#pragma unroll
    for (int i = 0; i < 8; i++)
#pragma unroll
        for (int j = 0; j < 4; j++)
            pout[(r0+i)*128 + c0 + j] = acc[i][j];
}

__global__ void reduce1(const float* __restrict__ part, const float* __restrict__ bias,
                        float* __restrict__ out)
{
    int idx = blockIdx.x*256 + threadIdx.x;   // 0..8191  (r*128 + c)
    float a = bias[idx & 127];
    for (int s = 0; s < NSPLIT; s++) a += part[s*8192 + idx];
    out[idx] = lreluf(a);
}

// small dense: (64 x 128) @ (128 x N), optional leaky relu
__global__ void dense_small(const float* __restrict__ xin, const float* __restrict__ w,
                            const float* __restrict__ bias, float* __restrict__ out,
                            int N, int relu)
{
    __shared__ float xs[128];
    const int b = blockIdx.x;
    xs[threadIdx.x] = xin[b*128 + threadIdx.x];
    __syncthreads();
    const int n = threadIdx.x;
    if (n < N) {
        float a = bias[n];
#pragma unroll 8
        for (int k = 0; k < 128; k++) a += xs[k] * w[k*N + n];
        if (relu) a = lreluf(a);
        out[b*N + n] = a;
    }
}

// ---------------------------------------------------------------------------
// Launch
// ---------------------------------------------------------------------------
extern "C" void kernel_launch(void* const* d_in, const int* in_sizes, int n_in,
                              void* d_out, int out_size)
{
    const float* x    = (const float*)d_in[0];
    const float* wx1  = (const float*)d_in[1];
    const float* wh1  = (const float*)d_in[2];
    const float* b1   = (const float*)d_in[3];
    const float* g1   = (const float*)d_in[4];
    const float* bt1  = (const float*)d_in[5];
    const float* m1   = (const float*)d_in[6];
    const float* v1   = (const float*)d_in[7];
    const float* wx2  = (const float*)d_in[8];
    const float* wh2  = (const float*)d_in[9];
    const float* b2   = (const float*)d_in[10];
    const float* g2   = (const float*)d_in[11];
    const float* bt2  = (const float*)d_in[12];
    const float* m2   = (const float*)d_in[13];
    const float* v2   = (const float*)d_in[14];
    const float* wx3  = (const float*)d_in[15];
    const float* wh3  = (const float*)d_in[16];
    const float* b3   = (const float*)d_in[17];
    const float* g3   = (const float*)d_in[18];
    const float* bt3  = (const float*)d_in[19];
    const float* m3   = (const float*)d_in[20];
    const float* v3   = (const float*)d_in[21];
    const float* w_d1 = (const float*)d_in[22];
    const float* b_d1 = (const float*)d_in[23];
    const float* w_d2 = (const float*)d_in[24];
    const float* b_d2 = (const float*)d_in[25];
    const float* w_d3 = (const float*)d_in[26];
    const float* b_d3 = (const float*)d_in[27];
    const float* w_o  = (const float*)d_in[28];
    const float* b_o  = (const float*)d_in[29];

    float4 *seqA, *seqB, *hA, *hB, *hbn;
    float  *part, *d1, *d2, *d3;
    cudaGetSymbolAddress((void**)&seqA, g_seqA);
    cudaGetSymbolAddress((void**)&seqB, g_seqB);
    cudaGetSymbolAddress((void**)&hA,   g_hA);
    cudaGetSymbolAddress((void**)&hB,   g_hB);
    cudaGetSymbolAddress((void**)&hbn,  g_hbn);
    cudaGetSymbolAddress((void**)&part, g_part);
    cudaGetSymbolAddress((void**)&d1,   g_d1);
    cudaGetSymbolAddress((void**)&d2,   g_d2);
    cudaGetSymbolAddress((void**)&d3,   g_d3);

    dim3 grid(WW/TW, HH/TILH, BB);   // (4, 8, 64)

    // ---- layer 1 (Cin=3): x -> seqA (BN applied on write) ----
    lstm_step<3,true ,1><<<grid,128>>>(x, TT*PIX, wx1, wh1, b1, g1,bt1,m1,v1,
                                       nullptr, hB, seqA, TT*PIX);
    for (int t = 1; t < TT; t++) {
        const float4* hin  = (t & 1) ? hB : hA;
        float4*       hout = (t & 1) ? hA : hB;
        lstm_step<3,false,1><<<grid,128>>>(x + (long)t*PIX*3, TT*PIX, wx1, wh1, b1,
                                           g1,bt1,m1,v1, hin, hout,
                                           seqA + (long)t*PIX, TT*PIX);
    }

    // ---- layer 2 (Cin=4): seqA -> seqB ----
    lstm_step<4,true ,1><<<grid,128>>>((const float*)seqA, TT*PIX, wx2, wh2, b2,
                                       g2,bt2,m2,v2, nullptr, hB, seqB, TT*PIX);
    for (int t = 1; t < TT; t++) {
        const float4* hin  = (t & 1) ? hB : hA;
        float4*       hout = (t & 1) ? hA : hB;
        lstm_step<4,false,1><<<grid,128>>>((const float*)(seqA + (long)t*PIX), TT*PIX,
                                           wx2, wh2, b2, g2,bt2,m2,v2,
                                           hin, hout, seqB + (long)t*PIX, TT*PIX);
    }

    // ---- layer 3 (Cin=4): seqB -> hbn (only final h, BN + leaky relu) ----
    lstm_step<4,true ,0><<<grid,128>>>((const float*)seqB, TT*PIX, wx3, wh3, b3,
                                       g3,bt3,m3,v3, nullptr, hB, nullptr, 0);
    for (int t = 1; t < TT-1; t++) {
        const float4* hin  = (t & 1) ? hB : hA;
        float4*       hout = (t & 1) ? hA : hB;
        lstm_step<4,false,0><<<grid,128>>>((const float*)(seqB + (long)t*PIX), TT*PIX,
                                           wx3, wh3, b3, g3,bt3,m3,v3,
                                           hin, hout, nullptr, 0);
    }
    {
        const int t = TT-1;  // t = 4: read hA (t&1==0), write hB, emit BN+lrelu
        lstm_step<4,false,2><<<grid,128>>>((const float*)(seqB + (long)t*PIX), TT*PIX,
                                           wx3, wh3, b3, g3,bt3,m3,v3,
                                           hA, hB, hbn, PIX);
    }

    // ---- dense head ----
    gemm1_part<<<NSPLIT,256>>>((const float*)hbn, w_d1, part);
    reduce1<<<32,256>>>(part, b_d1, d1);
    dense_small<<<BB,128>>>(d1, w_d2, b_d2, d2, 128, 1);
    dense_small<<<BB,128>>>(d2, w_d3, b_d3, d3, 128, 1);
    dense_small<<<BB,128>>>(d3, w_o,  b_o,  (float*)d_out, 2, 0);
}

// round 5
// speedup vs baseline: 1.3674x; 1.0497x over previous
#include <cuda_runtime.h>
#include <math.h>
#include <stdint.h>

// ---------------------------------------------------------------------------
// Problem constants
// ---------------------------------------------------------------------------
#define HH   128
#define WW   128
#define BB   64
#define TT   5
#define PIX  (HH*WW)        // 16384 pixels per image

// lstm tile: 32 wide x 16 tall. Block = 256 threads:
//   128 "strip" slots (32 tx x 4 ty, each strip = 4-pixel vertical run)
//   x 2 gate-halves (hf=0 -> couts 0-7 (i,f), hf=1 -> couts 8-15 (g,o))
#define TW   32
#define THY  4
#define PPT  4
#define TILH (THY*PPT)      // 16

#define NSPLIT 256          // split-K slices for dense1
#define KS     256          // K per slice (256*256 = 65536)

// ---------------------------------------------------------------------------
// Static device scratch (no allocations allowed)
// ---------------------------------------------------------------------------
__device__ float4 g_seqA[BB*TT*PIX];    // layer1 output (BN applied), (B,T,H,W,4)
__device__ float4 g_seqB[BB*TT*PIX];    // layer2 output (BN applied)
__device__ float4 g_hA[BB*PIX];         // recurrent h double-buffer
__device__ float4 g_hB[BB*PIX];
__device__ float4 g_cS[BB*PIX];         // cell state (in-place safe: own-pixel only)
__device__ float4 g_hbn[BB*PIX];        // lrelu(bn(h_last))  == flattened (B,65536)
__device__ float  g_part[NSPLIT*BB*128];// dense1 split-K partials
__device__ float  g_d1[BB*128];
__device__ float  g_d2[BB*128];
__device__ float  g_d3[BB*128];

// ---------------------------------------------------------------------------
// Packed f32x2 helpers (Blackwell packed fp32 FMA — only via explicit PTX)
// ---------------------------------------------------------------------------
__device__ __forceinline__ uint64_t pack2(float lo, float hi) {
    uint64_t r;
    asm("mov.b64 %0, {%1, %2};" : "=l"(r) : "f"(lo), "f"(hi));
    return r;
}
__device__ __forceinline__ void fma2(uint64_t& d, uint64_t a, uint64_t b) {
    asm("fma.rn.f32x2 %0, %1, %2, %0;" : "+l"(d) : "l"(a), "l"(b));
}
__device__ __forceinline__ float2 unpack2(uint64_t v) {
    float2 r;
    asm("mov.b64 {%0, %1}, %2;" : "=f"(r.x), "=f"(r.y) : "l"(v));
    return r;
}

// ---------------------------------------------------------------------------
// Fast activations (abs err ~1e-7 — far below the 1e-3 gate).
// ---------------------------------------------------------------------------
__device__ __forceinline__ float sigf(float x) {
    return __fdividef(1.0f, 1.0f + __expf(-x));
}
__device__ __forceinline__ float tanhfast(float x) {
    float e = __expf(-2.0f * fabsf(x));
    float r = __fdividef(1.0f - e, 1.0f + e);
    return copysignf(r, x);
}
__device__ __forceinline__ float lreluf(float x) { return x > 0.0f ? x : 0.3f * x; }

__device__ __forceinline__ float getc(float4 v, int ci) {
    return (ci == 0) ? v.x : (ci == 1) ? v.y : (ci == 2) ? v.z : v.w;
}

// ---------------------------------------------------------------------------
// One ConvLSTM2D timestep, 2-way gate-split:
// each (tx,ty) strip is computed by two threads; each holds 8 couts as
// 4 f32x2 pairs (32 regs instead of 64) -> occupancy 3 blocks/SM.
// hf=1 ships its g/o pre-activations to hf=0 through SMEM (aliased over the
// dead tile buffers); hf=0 runs the LSTM epilogue.
// ---------------------------------------------------------------------------
template<int CINSRC, bool FIRST, int MODE>
__global__ __launch_bounds__(256, 3)
void lstm_step(const float* __restrict__ xin, int x_pxb,
               const float* __restrict__ wx, const float* __restrict__ wh,
               const float* __restrict__ bias,
               const float* __restrict__ bng, const float* __restrict__ bnb,
               const float* __restrict__ bnm, const float* __restrict__ bnv,
               const float4* __restrict__ hin, float4* __restrict__ hout,
               float4* __restrict__ seq_out, int s_pxb)
{
    __shared__ float4 s_wx4[144];            // [tap][ci(4, zero-padded)][j(4)] -> 16 couts
    __shared__ float4 s_wh4[144];
    __shared__ float  s_bias[16];
    __shared__ float  s_scale[4], s_shift[4];
    // tiles; after the conv loops this region is re-used as the gate-exchange
    // buffer (needs 4*512*8 = 16384 B <= 19584 B)
    __shared__ float4 s_tiles[2][TILH+2][TW+2];   // [0]=x, [1]=h
#define s_xt (s_tiles[0])
#define s_ht (s_tiles[1])

    const int tid = threadIdx.x;
    const int b   = blockIdx.z;
    const int ty0 = blockIdx.y * TILH;
    const int tx0 = blockIdx.x * TW;

    // ---- stage weights ----
    {
        float* s_wxf = (float*)s_wx4;
        for (int i = tid; i < 576; i += 256) {
            int tap = i >> 6, r = i & 63, ci = r >> 4, co = r & 15;
            s_wxf[i] = (ci < CINSRC) ? wx[(tap*CINSRC + ci)*16 + co] : 0.0f;
        }
        if (!FIRST) {
            float* s_whf = (float*)s_wh4;
            for (int i = tid; i < 576; i += 256) s_whf[i] = wh[i];
        }
        if (tid < 16) s_bias[tid] = bias[tid];
        if (MODE != 0 && tid < 4) {
            float sc = bng[tid] * rsqrtf(bnv[tid] + 1e-3f);
            s_scale[tid] = sc;
            s_shift[tid] = bnb[tid] - bnm[tid]*sc;
        }
    }

    // ---- stage x / h tiles with halo (zero padded) ----
    const float4* x4 = reinterpret_cast<const float4*>(xin);
    for (int i = tid; i < (TILH+2)*(TW+2); i += 256) {
        int ly = i / (TW+2), lx = i % (TW+2);
        int gy = ty0 + ly - 1, gx = tx0 + lx - 1;
        bool ok = (gy >= 0) && (gy < HH) && (gx >= 0) && (gx < WW);
        float4 xv = make_float4(0.f,0.f,0.f,0.f);
        float4 hv = make_float4(0.f,0.f,0.f,0.f);
        if (ok) {
            if (CINSRC == 4) {
                xv = x4[(long)b*x_pxb + gy*WW + gx];
            } else {
                const float* p = xin + ((long)b*x_pxb + gy*WW + gx)*3;
                xv.x = p[0]; xv.y = p[1]; xv.z = p[2];
            }
            if (!FIRST) hv = hin[b*PIX + gy*WW + gx];
        }
        s_xt[ly][lx] = xv;
        if (!FIRST) s_ht[ly][lx] = hv;
    }
    __syncthreads();

    const int hf = tid >> 7;          // gate half: 0 -> couts 0-7, 1 -> couts 8-15
    const int st = tid & 127;         // strip slot
    const int tx = st & 31;           // 0..31
    const int ty = st >> 5;           // 0..3
    const int ry = ty * PPT;          // base row in tile

    // accumulators: acc2[p][j] holds couts (8*hf + 2j, 8*hf + 2j + 1)
    uint64_t acc2[PPT][4];
    {
        uint64_t binit[4];
#pragma unroll
        for (int j = 0; j < 4; j++)
            binit[j] = pack2(s_bias[8*hf + 2*j], s_bias[8*hf + 2*j + 1]);
#pragma unroll
        for (int p = 0; p < PPT; p++)
#pragma unroll
            for (int j = 0; j < 4; j++) acc2[p][j] = binit[j];
    }

    const int CIMAX = (CINSRC == 3) ? 3 : 4;

    // ---- x conv ----
#pragma unroll
    for (int dx = 0; dx < 3; dx++) {
        float4 colv[PPT+2];
#pragma unroll
        for (int r = 0; r < PPT+2; r++) colv[r] = s_xt[ry + r][tx + dx];
#pragma unroll
        for (int dy = 0; dy < 3; dy++) {
            const int tap = dy*3 + dx;
#pragma unroll
            for (int ci = 0; ci < CIMAX; ci++) {
                const ulonglong2* wp =
                    reinterpret_cast<const ulonglong2*>(&s_wx4[(tap*4 + ci)*4]);
                ulonglong2 wA = wp[2*hf];       // this half's couts (4 of them)
                ulonglong2 wB = wp[2*hf + 1];   // next 4
#pragma unroll
                for (int p = 0; p < PPT; p++) {
                    float val = getc(colv[dy + p], ci);
                    uint64_t vv = pack2(val, val);
                    fma2(acc2[p][0], vv, wA.x); fma2(acc2[p][1], vv, wA.y);
                    fma2(acc2[p][2], vv, wB.x); fma2(acc2[p][3], vv, wB.y);
                }
            }
        }
    }

    // ---- h conv ----
    if (!FIRST) {
#pragma unroll
        for (int dx = 0; dx < 3; dx++) {
            float4 colv[PPT+2];
#pragma unroll
            for (int r = 0; r < PPT+2; r++) colv[r] = s_ht[ry + r][tx + dx];
#pragma unroll
            for (int dy = 0; dy < 3; dy++) {
                const int tap = dy*3 + dx;
#pragma unroll
                for (int ci = 0; ci < 4; ci++) {
                    const ulonglong2* wp =
                        reinterpret_cast<const ulonglong2*>(&s_wh4[(tap*4 + ci)*4]);
                    ulonglong2 wA = wp[2*hf];
                    ulonglong2 wB = wp[2*hf + 1];
#pragma unroll
                    for (int p = 0; p < PPT; p++) {
                        float val = getc(colv[dy + p], ci);
                        uint64_t vv = pack2(val, val);
                        fma2(acc2[p][0], vv, wA.x); fma2(acc2[p][1], vv, wA.y);
                        fma2(acc2[p][2], vv, wB.x); fma2(acc2[p][3], vv, wB.y);
                    }
                }
            }
        }
    }

    // ---- exchange: hf=1 publishes g/o pre-activations over the tile smem ----
    __syncthreads();   // all tile reads done; safe to alias
    uint64_t* s_ex = reinterpret_cast<uint64_t*>(&s_tiles[0][0][0]);  // [4][512]
    if (hf == 1) {
#pragma unroll
        for (int p = 0; p < PPT; p++) {
            const int idx = (ry + p)*TW + tx;   // 0..511
#pragma unroll
            for (int j = 0; j < 4; j++) s_ex[j*512 + idx] = acc2[p][j];
        }
    }
    __syncthreads();

    // ---- epilogue (hf=0 threads only) ----
    if (hf == 0) {
#pragma unroll
        for (int p = 0; p < PPT; p++) {
            const int idx  = (ry + p)*TW + tx;
            const int pix  = (ty0 + ry + p)*WW + (tx0 + tx);
            const int sidx = b*PIX + pix;

            float zi[4], zf[4], zg[4], zo[4];
#pragma unroll
            for (int j = 0; j < 4; j++) {
                float2 u = unpack2(acc2[p][j]);   // couts 2j, 2j+1 (i,f half)
                if (j < 2) { zi[2*j] = u.x; zi[2*j+1] = u.y; }
                else       { zf[2*(j-2)] = u.x; zf[2*(j-2)+1] = u.y; }
            }
            {
                float2 u;
                u = unpack2(s_ex[0*512 + idx]); zg[0] = u.x; zg[1] = u.y;
                u = unpack2(s_ex[1*512 + idx]); zg[2] = u.x; zg[3] = u.y;
                u = unpack2(s_ex[2*512 + idx]); zo[0] = u.x; zo[1] = u.y;
                u = unpack2(s_ex[3*512 + idx]); zo[2] = u.x; zo[3] = u.y;
            }

            float cold[4] = {0.f, 0.f, 0.f, 0.f};
            if (!FIRST) {
                float4 t = g_cS[sidx];
                cold[0]=t.x; cold[1]=t.y; cold[2]=t.z; cold[3]=t.w;
            }

            float cn[4], hn[4];
#pragma unroll
            for (int c = 0; c < 4; c++) {
                float iv = sigf(zi[c]);
                float fv = sigf(zf[c]);
                float gv = tanhfast(zg[c]);
                float ov = sigf(zo[c]);
                float cc = fv*cold[c] + iv*gv;
                cn[c] = cc;
                hn[c] = ov * tanhfast(cc);
            }
            g_cS[sidx] = make_float4(cn[0], cn[1], cn[2], cn[3]);
            hout[sidx] = make_float4(hn[0], hn[1], hn[2], hn[3]);

            if (MODE != 0) {
                float o[4];
#pragma unroll
                for (int c = 0; c < 4; c++) {
                    float v = s_scale[c]*hn[c] + s_shift[c];
                    if (MODE == 2) v = lreluf(v);
                    o[c] = v;
                }
                seq_out[(long)b*s_pxb + pix] = make_float4(o[0], o[1], o[2], o[3]);
            }
        }
    }
#undef s_xt
#undef s_ht
}

// ---------------------------------------------------------------------------
// dense1: (64 x 65536) @ (65536 x 128) — split-K partials (deterministic)
// ---------------------------------------------------------------------------
__global__ __launch_bounds__(256)
void gemm1_part(const float* __restrict__ A, const float* __restrict__ Wm,
                float* __restrict__ part)
{
    __shared__ __align__(16) float xs[64][32];
    __shared__ __align__(16) float ws[32][128];

    const int tid   = threadIdx.x;
    const int s     = blockIdx.x;
    const int kbase = s * KS;
    const int r0    = (tid >> 5) * 8;   // 8 warps -> 8 row groups of 8
    const int c0    = (tid & 31) * 4;   // 32 lanes -> 128 cols in float4

    float acc[8][4];
#pragma unroll
    for (int i = 0; i < 8; i++)
#pragma unroll
        for (int j = 0; j < 4; j++) acc[i][j] = 0.f;

    for (int ch = 0; ch < KS/32; ch++) {
        const int k0 = kbase + ch*32;
        for (int i = tid; i < 64*32; i += 256) {
            int r = i >> 5, kk = i & 31;
            xs[r][kk] = A[(long)r*65536 + k0 + kk];
        }
        for (int i = tid; i < 32*128; i += 256) {
            int kk = i >> 7, n = i & 127;
            ws[kk][n] = Wm[(long)(k0 + kk)*128 + n];
        }
        __syncthreads();
#pragma unroll
        for (int kk = 0; kk < 32; kk++) {
            float4 wv = *reinterpret_cast<const float4*>(&ws[kk][c0]);
#pragma unroll
            for (int i = 0; i < 8; i++) {
                float a = xs[r0+i][kk];
                acc[i][0] += a*wv.x; acc[i][1] += a*wv.y;
                acc[i][2] += a*wv.z; acc[i][3] += a*wv.w;
            }
        }
        __syncthreads();
    }

    float* pout = part + (long)s*8192;
#pragma unroll
    for (int i = 0; i < 8; i++)
#pragma unroll
        for (int j = 0; j < 4; j++)
            pout[(r0+i)*128 + c0 + j] = acc[i][j];
}

__global__ void reduce1(const float* __restrict__ part, const float* __restrict__ bias,
                        float* __restrict__ out)
{
    int idx = blockIdx.x*256 + threadIdx.x;   // 0..8191  (r*128 + c)
    float a = bias[idx & 127];
    for (int s = 0; s < NSPLIT; s++) a += part[s*8192 + idx];
    out[idx] = lreluf(a);
}

// small dense: (64 x 128) @ (128 x N), optional leaky relu
__global__ void dense_small(const float* __restrict__ xin, const float* __restrict__ w,
                            const float* __restrict__ bias, float* __restrict__ out,
                            int N, int relu)
{
    __shared__ float xs[128];
    const int b = blockIdx.x;
    xs[threadIdx.x] = xin[b*128 + threadIdx.x];
    __syncthreads();
    const int n = threadIdx.x;
    if (n < N) {
        float a = bias[n];
#pragma unroll 8
        for (int k = 0; k < 128; k++) a += xs[k] * w[k*N + n];
        if (relu) a = lreluf(a);
        out[b*N + n] = a;
    }
}

// ---------------------------------------------------------------------------
// Launch
// ---------------------------------------------------------------------------
extern "C" void kernel_launch(void* const* d_in, const int* in_sizes, int n_in,
                              void* d_out, int out_size)
{
    const float* x    = (const float*)d_in[0];
    const float* wx1  = (const float*)d_in[1];
    const float* wh1  = (const float*)d_in[2];
    const float* b1   = (const float*)d_in[3];
    const float* g1   = (const float*)d_in[4];
    const float* bt1  = (const float*)d_in[5];
    const float* m1   = (const float*)d_in[6];
    const float* v1   = (const float*)d_in[7];
    const float* wx2  = (const float*)d_in[8];
    const float* wh2  = (const float*)d_in[9];
    const float* b2   = (const float*)d_in[10];
    const float* g2   = (const float*)d_in[11];
    const float* bt2  = (const float*)d_in[12];
    const float* m2   = (const float*)d_in[13];
    const float* v2   = (const float*)d_in[14];
    const float* wx3  = (const float*)d_in[15];
    const float* wh3  = (const float*)d_in[16];
    const float* b3   = (const float*)d_in[17];
    const float* g3   = (const float*)d_in[18];
    const float* bt3  = (const float*)d_in[19];
    const float* m3   = (const float*)d_in[20];
    const float* v3   = (const float*)d_in[21];
    const float* w_d1 = (const float*)d_in[22];
    const float* b_d1 = (const float*)d_in[23];
    const float* w_d2 = (const float*)d_in[24];
    const float* b_d2 = (const float*)d_in[25];
    const float* w_d3 = (const float*)d_in[26];
    const float* b_d3 = (const float*)d_in[27];
    const float* w_o  = (const float*)d_in[28];
    const float* b_o  = (const float*)d_in[29];

    float4 *seqA, *seqB, *hA, *hB, *hbn;
    float  *part, *d1, *d2, *d3;
    cudaGetSymbolAddress((void**)&seqA, g_seqA);
    cudaGetSymbolAddress((void**)&seqB, g_seqB);
    cudaGetSymbolAddress((void**)&hA,   g_hA);
    cudaGetSymbolAddress((void**)&hB,   g_hB);
    cudaGetSymbolAddress((void**)&hbn,  g_hbn);
    cudaGetSymbolAddress((void**)&part, g_part);
    cudaGetSymbolAddress((void**)&d1,   g_d1);
    cudaGetSymbolAddress((void**)&d2,   g_d2);
    cudaGetSymbolAddress((void**)&d3,   g_d3);

    dim3 grid(WW/TW, HH/TILH, BB);   // (4, 8, 64)

    // ---- layer 1 (Cin=3): x -> seqA (BN applied on write) ----
    lstm_step<3,true ,1><<<grid,256>>>(x, TT*PIX, wx1, wh1, b1, g1,bt1,m1,v1,
                                       nullptr, hB, seqA, TT*PIX);
    for (int t = 1; t < TT; t++) {
        const float4* hin  = (t & 1) ? hB : hA;
        float4*       hout = (t & 1) ? hA : hB;
        lstm_step<3,false,1><<<grid,256>>>(x + (long)t*PIX*3, TT*PIX, wx1, wh1, b1,
                                           g1,bt1,m1,v1, hin, hout,
                                           seqA + (long)t*PIX, TT*PIX);
    }

    // ---- layer 2 (Cin=4): seqA -> seqB ----
    lstm_step<4,true ,1><<<grid,256>>>((const float*)seqA, TT*PIX, wx2, wh2, b2,
                                       g2,bt2,m2,v2, nullptr, hB, seqB, TT*PIX);
    for (int t = 1; t < TT; t++) {
        const float4* hin  = (t & 1) ? hB : hA;
        float4*       hout = (t & 1) ? hA : hB;
        lstm_step<4,false,1><<<grid,256>>>((const float*)(seqA + (long)t*PIX), TT*PIX,
                                           wx2, wh2, b2, g2,bt2,m2,v2,
                                           hin, hout, seqB + (long)t*PIX, TT*PIX);
    }

    // ---- layer 3 (Cin=4): seqB -> hbn (only final h, BN + leaky relu) ----
    lstm_step<4,true ,0><<<grid,256>>>((const float*)seqB, TT*PIX, wx3, wh3, b3,
                                       g3,bt3,m3,v3, nullptr, hB, nullptr, 0);
    for (int t = 1; t < TT-1; t++) {
        const float4* hin  = (t & 1) ? hB : hA;
        float4*       hout = (t & 1) ? hA : hB;
        lstm_step<4,false,0><<<grid,256>>>((const float*)(seqB + (long)t*PIX), TT*PIX,
                                           wx3, wh3, b3, g3,bt3,m3,v3,
                                           hin, hout, nullptr, 0);
    }
    {
        const int t = TT-1;  // t = 4: read hA (t&1==0), write hB, emit BN+lrelu
        lstm_step<4,false,2><<<grid,256>>>((const float*)(seqB + (long)t*PIX), TT*PIX,
                                           wx3, wh3, b3, g3,bt3,m3,v3,
                                           hA, hB, hbn, PIX);
    }

    // ---- dense head ----
    gemm1_part<<<NSPLIT,256>>>((const float*)hbn, w_d1, part);
    reduce1<<<32,256>>>(part, b_d1, d1);
    dense_small<<<BB,128>>>(d1, w_d2, b_d2, d2, 128, 1);
    dense_small<<<BB,128>>>(d2, w_d3, b_d3, d3, 128, 1);
    dense_small<<<BB,128>>>(d3, w_o,  b_o,  (float*)d_out, 2, 0);
}

// round 7
// speedup vs baseline: 1.4043x; 1.0270x over previous
#include <cuda_runtime.h>
#include <math.h>
#include <stdint.h>

// ---------------------------------------------------------------------------
// Problem constants
// ---------------------------------------------------------------------------
#define HH   128
#define WW   128
#define BB   64
#define TT   5
#define PIX  (HH*WW)        // 16384 pixels per image

// lstm tile: block = 128 threads (32 x 4), each thread computes a 2-pixel
// vertical strip -> tile = 32 wide x 8 tall
#define TW   32
#define THY  4
#define PPT  2
#define TILH (THY*PPT)      // 8

#define NSPLIT 256          // split-K slices for dense1
#define KS     256          // K per slice (256*256 = 65536)

// ---------------------------------------------------------------------------
// Static device scratch (no allocations allowed)
// ---------------------------------------------------------------------------
__device__ float4 g_seqA[BB*TT*PIX];    // layer1 output (BN applied), (B,T,H,W,4)
__device__ float4 g_seqB[BB*TT*PIX];    // layer2 output (BN applied)
__device__ float4 g_hA[BB*PIX];         // recurrent h double-buffer
__device__ float4 g_hB[BB*PIX];
__device__ float4 g_cS[BB*PIX];         // cell state (in-place safe: own-pixel only)
__device__ float4 g_hbn[BB*PIX];        // lrelu(bn(h_last))  == flattened (B,65536)
__device__ float  g_part[NSPLIT*BB*128];// dense1 split-K partials
__device__ float  g_d1[BB*128];
__device__ float  g_d2[BB*128];
__device__ float  g_d3[BB*128];

// ---------------------------------------------------------------------------
// Packed f32x2 helpers (Blackwell packed fp32 FMA — only via explicit PTX)
// ---------------------------------------------------------------------------
__device__ __forceinline__ uint64_t pack2(float lo, float hi) {
    uint64_t r;
    asm("mov.b64 %0, {%1, %2};" : "=l"(r) : "f"(lo), "f"(hi));
    return r;
}
__device__ __forceinline__ void fma2(uint64_t& d, uint64_t a, uint64_t b) {
    asm("fma.rn.f32x2 %0, %1, %2, %0;" : "+l"(d) : "l"(a), "l"(b));
}
__device__ __forceinline__ float2 unpack2(uint64_t v) {
    float2 r;
    asm("mov.b64 {%0, %1}, %2;" : "=f"(r.x), "=f"(r.y) : "l"(v));
    return r;
}

// ---------------------------------------------------------------------------
// Fast activations (abs err ~1e-7 — far below the 1e-3 gate).
// ---------------------------------------------------------------------------
__device__ __forceinline__ float sigf(float x) {
    return __fdividef(1.0f, 1.0f + __expf(-x));
}
__device__ __forceinline__ float tanhfast(float x) {
    float e = __expf(-2.0f * fabsf(x));
    float r = __fdividef(1.0f - e, 1.0f + e);
    return copysignf(r, x);
}
__device__ __forceinline__ float lreluf(float x) { return x > 0.0f ? x : 0.3f * x; }

__device__ __forceinline__ float getc(float4 v, int ci) {
    return (ci == 0) ? v.x : (ci == 1) ? v.y : (ci == 2) ? v.z : v.w;
}

// ---------------------------------------------------------------------------
// One ConvLSTM2D timestep (fused: x-conv + h-conv + gates + state + BN write)
//   CINSRC : input channels of x (3 for layer1, 4 for layers 2/3)
//   FIRST  : t==0 -> h=c=0, skip h-conv and state reads
//   MODE   : 0 = no seq write, 1 = write bn(h) to seq_out, 2 = write lrelu(bn(h))
// Each thread owns a 2-pixel vertical strip and all 16 couts as 8 f32x2
// pairs (32 regs of acc) -> >=6 CTAs/SM (37.5% occupancy), no gate split,
// no extra barriers. Weight LDS are warp-broadcast (free on the crossbar).
// ---------------------------------------------------------------------------
template<int CINSRC, bool FIRST, int MODE>
__global__ __launch_bounds__(128, 6)
void lstm_step(const float* __restrict__ xin, int x_pxb,
               const float* __restrict__ wx, const float* __restrict__ wh,
               const float* __restrict__ bias,
               const float* __restrict__ bng, const float* __restrict__ bnb,
               const float* __restrict__ bnm, const float* __restrict__ bnv,
               const float4* __restrict__ hin, float4* __restrict__ hout,
               float4* __restrict__ seq_out, int s_pxb)
{
    __shared__ float4 s_wx4[144];            // [tap][ci(4, zero-padded)][j(4)] -> 16 couts
    __shared__ float4 s_wh4[144];
    __shared__ float  s_bias[16];
    __shared__ float  s_scale[4], s_shift[4];
    __shared__ float4 s_xt[TILH+2][TW+2];    // 10 x 34
    __shared__ float4 s_ht[TILH+2][TW+2];

    const int tid = threadIdx.x;
    const int b   = blockIdx.z;
    const int ty0 = blockIdx.y * TILH;
    const int tx0 = blockIdx.x * TW;

    // ---- stage weights ----
    {
        float* s_wxf = (float*)s_wx4;
        for (int i = tid; i < 576; i += 128) {
            int tap = i >> 6, r = i & 63, ci = r >> 4, co = r & 15;
            s_wxf[i] = (ci < CINSRC) ? wx[(tap*CINSRC + ci)*16 + co] : 0.0f;
        }
        if (!FIRST) {
            float* s_whf = (float*)s_wh4;
            for (int i = tid; i < 576; i += 128) s_whf[i] = wh[i];
        }
        if (tid < 16) s_bias[tid] = bias[tid];
        if (MODE != 0 && tid < 4) {
            float sc = bng[tid] * rsqrtf(bnv[tid] + 1e-3f);
            s_scale[tid] = sc;
            s_shift[tid] = bnb[tid] - bnm[tid]*sc;
        }
    }

    // ---- stage x / h tiles with halo (zero padded) ----
    const float4* x4 = reinterpret_cast<const float4*>(xin);
    for (int i = tid; i < (TILH+2)*(TW+2); i += 128) {
        int ly = i / (TW+2), lx = i % (TW+2);
        int gy = ty0 + ly - 1, gx = tx0 + lx - 1;
        bool ok = (gy >= 0) && (gy < HH) && (gx >= 0) && (gx < WW);
        float4 xv = make_float4(0.f,0.f,0.f,0.f);
        float4 hv = make_float4(0.f,0.f,0.f,0.f);
        if (ok) {
            if (CINSRC == 4) {
                xv = x4[(long)b*x_pxb + gy*WW + gx];
            } else {
                const float* p = xin + ((long)b*x_pxb + gy*WW + gx)*3;
                xv.x = p[0]; xv.y = p[1]; xv.z = p[2];
            }
            if (!FIRST) hv = hin[b*PIX + gy*WW + gx];
        }
        s_xt[ly][lx] = xv;
        if (!FIRST) s_ht[ly][lx] = hv;
    }
    __syncthreads();

    const int tx = tid & 31;        // 0..31
    const int ty = tid >> 5;        // 0..3
    const int ry = ty * PPT;        // base row in tile

    // accumulators: acc2[p][j] holds couts (2j, 2j+1)
    uint64_t acc2[PPT][8];
    {
        uint64_t binit[8];
#pragma unroll
        for (int j = 0; j < 8; j++) binit[j] = pack2(s_bias[2*j], s_bias[2*j+1]);
#pragma unroll
        for (int p = 0; p < PPT; p++)
#pragma unroll
            for (int j = 0; j < 8; j++) acc2[p][j] = binit[j];
    }

    const int CIMAX = (CINSRC == 3) ? 3 : 4;

    // ---- x conv ----
#pragma unroll
    for (int dx = 0; dx < 3; dx++) {
        float4 colv[PPT+2];
#pragma unroll
        for (int r = 0; r < PPT+2; r++) colv[r] = s_xt[ry + r][tx + dx];
#pragma unroll
        for (int dy = 0; dy < 3; dy++) {
            const int tap = dy*3 + dx;
#pragma unroll
            for (int ci = 0; ci < CIMAX; ci++) {
                const ulonglong2* wp =
                    reinterpret_cast<const ulonglong2*>(&s_wx4[(tap*4 + ci)*4]);
                ulonglong2 wA = wp[0];   // couts 0..3  (two f32x2 pairs)
                ulonglong2 wB = wp[1];   // couts 4..7
                ulonglong2 wC = wp[2];   // couts 8..11
                ulonglong2 wD = wp[3];   // couts 12..15
#pragma unroll
                for (int p = 0; p < PPT; p++) {
                    float val = getc(colv[dy + p], ci);
                    uint64_t vv = pack2(val, val);
                    fma2(acc2[p][0], vv, wA.x); fma2(acc2[p][1], vv, wA.y);
                    fma2(acc2[p][2], vv, wB.x); fma2(acc2[p][3], vv, wB.y);
                    fma2(acc2[p][4], vv, wC.x); fma2(acc2[p][5], vv, wC.y);
                    fma2(acc2[p][6], vv, wD.x); fma2(acc2[p][7], vv, wD.y);
                }
            }
        }
    }

    // ---- h conv ----
    if (!FIRST) {
#pragma unroll
        for (int dx = 0; dx < 3; dx++) {
            float4 colv[PPT+2];
#pragma unroll
            for (int r = 0; r < PPT+2; r++) colv[r] = s_ht[ry + r][tx + dx];
#pragma unroll
            for (int dy = 0; dy < 3; dy++) {
                const int tap = dy*3 + dx;
#pragma unroll
                for (int ci = 0; ci < 4; ci++) {
                    const ulonglong2* wp =
                        reinterpret_cast<const ulonglong2*>(&s_wh4[(tap*4 + ci)*4]);
                    ulonglong2 wA = wp[0];
                    ulonglong2 wB = wp[1];
                    ulonglong2 wC = wp[2];
                    ulonglong2 wD = wp[3];
#pragma unroll
                    for (int p = 0; p < PPT; p++) {
                        float val = getc(colv[dy + p], ci);
                        uint64_t vv = pack2(val, val);
                        fma2(acc2[p][0], vv, wA.x); fma2(acc2[p][1], vv, wA.y);
                        fma2(acc2[p][2], vv, wB.x); fma2(acc2[p][3], vv, wB.y);
                        fma2(acc2[p][4], vv, wC.x); fma2(acc2[p][5], vv, wC.y);
                        fma2(acc2[p][6], vv, wD.x); fma2(acc2[p][7], vv, wD.y);
                    }
                }
            }
        }
    }

    // ---- gates + state + optional BN seq write, per strip pixel ----
#pragma unroll
    for (int p = 0; p < PPT; p++) {
        const int pix  = (ty0 + ry + p)*WW + (tx0 + tx);
        const int sidx = b*PIX + pix;

        float z[16];
#pragma unroll
        for (int j = 0; j < 8; j++) {
            float2 u = unpack2(acc2[p][j]);
            z[2*j]   = u.x;
            z[2*j+1] = u.y;
        }

        float cold[4] = {0.f, 0.f, 0.f, 0.f};
        if (!FIRST) {
            float4 t = g_cS[sidx];
            cold[0]=t.x; cold[1]=t.y; cold[2]=t.z; cold[3]=t.w;
        }

        float cn[4], hn[4];
#pragma unroll
        for (int c = 0; c < 4; c++) {
            float iv = sigf(z[c]);
            float fv = sigf(z[4+c]);
            float gv = tanhfast(z[8+c]);
            float ov = sigf(z[12+c]);
            float cc = fv*cold[c] + iv*gv;
            cn[c] = cc;
            hn[c] = ov * tanhfast(cc);
        }
        g_cS[sidx] = make_float4(cn[0], cn[1], cn[2], cn[3]);
        hout[sidx] = make_float4(hn[0], hn[1], hn[2], hn[3]);

        if (MODE != 0) {
            float o[4];
#pragma unroll
            for (int c = 0; c < 4; c++) {
                float v = s_scale[c]*hn[c] + s_shift[c];
                if (MODE == 2) v = lreluf(v);
                o[c] = v;
            }
            seq_out[(long)b*s_pxb + pix] = make_float4(o[0], o[1], o[2], o[3]);
        }
    }
}

// ---------------------------------------------------------------------------
// dense1: (64 x 65536) @ (65536 x 128) — split-K partials (deterministic)
// ---------------------------------------------------------------------------
__global__ __launch_bounds__(256)
void gemm1_part(const float* __restrict__ A, const float* __restrict__ Wm,
                float* __restrict__ part)
{
    __shared__ __align__(16) float xs[64][32];
    __shared__ __align__(16) float ws[32][128];

    const int tid   = threadIdx.x;
    const int s     = blockIdx.x;
    const int kbase = s * KS;
    const int r0    = (tid >> 5) * 8;   // 8 warps -> 8 row groups of 8
    const int c0    = (tid & 31) * 4;   // 32 lanes -> 128 cols in float4

    float acc[8][4];
#pragma unroll
    for (int i = 0; i < 8; i++)
#pragma unroll
        for (int j = 0; j < 4; j++) acc[i][j] = 0.f;

    for (int ch = 0; ch < KS/32; ch++) {
        const int k0 = kbase + ch*32;
        for (int i = tid; i < 64*32; i += 256) {
            int r = i >> 5, kk = i & 31;
            xs[r][kk] = A[(long)r*65536 + k0 + kk];
        }
        for (int i = tid; i < 32*128; i += 256) {
            int kk = i >> 7, n = i & 127;
            ws[kk][n] = Wm[(long)(k0 + kk)*128 + n];
        }
        __syncthreads();
#pragma unroll
        for (int kk = 0; kk < 32; kk++) {
            float4 wv = *reinterpret_cast<const float4*>(&ws[kk][c0]);
#pragma unroll
            for (int i = 0; i < 8; i++) {
                float a = xs[r0+i][kk];
                acc[i][0] += a*wv.x; acc[i][1] += a*wv.y;
                acc[i][2] += a*wv.z; acc[i][3] += a*wv.w;
            }
        }
        __syncthreads();
    }

    float* pout = part + (long)s*8192;
#pragma unroll
    for (int i = 0; i < 8; i++)
#pragma unroll
        for (int j = 0; j < 4; j++)
            pout[(r0+i)*128 + c0 + j] = acc[i][j];
}

__global__ void reduce1(const float* __restrict__ part, const float* __restrict__ bias,
                        float* __restrict__ out)
{
    int idx = blockIdx.x*256 + threadIdx.x;   // 0..8191  (r*128 + c)
    float a = bias[idx & 127];
    for (int s = 0; s < NSPLIT; s++) a += part[s*8192 + idx];
    out[idx] = lreluf(a);
}

// small dense: (64 x 128) @ (128 x N), optional leaky relu
__global__ void dense_small(const float* __restrict__ xin, const float* __restrict__ w,
                            const float* __restrict__ bias, float* __restrict__ out,
                            int N, int relu)
{
    __shared__ float xs[128];
    const int b = blockIdx.x;
    xs[threadIdx.x] = xin[b*128 + threadIdx.x];
    __syncthreads();
    const int n = threadIdx.x;
    if (n < N) {
        float a = bias[n];
#pragma unroll 8
        for (int k = 0; k < 128; k++) a += xs[k] * w[k*N + n];
        if (relu) a = lreluf(a);
        out[b*N + n] = a;
    }
}

// ---------------------------------------------------------------------------
// Launch
// ---------------------------------------------------------------------------
extern "C" void kernel_launch(void* const* d_in, const int* in_sizes, int n_in,
                              void* d_out, int out_size)
{
    const float* x    = (const float*)d_in[0];
    const float* wx1  = (const float*)d_in[1];
    const float* wh1  = (const float*)d_in[2];
    const float* b1   = (const float*)d_in[3];
    const float* g1   = (const float*)d_in[4];
    const float* bt1  = (const float*)d_in[5];
    const float* m1   = (const float*)d_in[6];
    const float* v1   = (const float*)d_in[7];
    const float* wx2  = (const float*)d_in[8];
    const float* wh2  = (const float*)d_in[9];
    const float* b2   = (const float*)d_in[10];
    const float* g2   = (const float*)d_in[11];
    const float* bt2  = (const float*)d_in[12];
    const float* m2   = (const float*)d_in[13];
    const float* v2   = (const float*)d_in[14];
    const float* wx3  = (const float*)d_in[15];
    const float* wh3  = (const float*)d_in[16];
    const float* b3   = (const float*)d_in[17];
    const float* g3   = (const float*)d_in[18];
    const float* bt3  = (const float*)d_in[19];
    const float* m3   = (const float*)d_in[20];
    const float* v3   = (const float*)d_in[21];
    const float* w_d1 = (const float*)d_in[22];
    const float* b_d1 = (const float*)d_in[23];
    const float* w_d2 = (const float*)d_in[24];
    const float* b_d2 = (const float*)d_in[25];
    const float* w_d3 = (const float*)d_in[26];
    const float* b_d3 = (const float*)d_in[27];
    const float* w_o  = (const float*)d_in[28];
    const float* b_o  = (const float*)d_in[29];

    float4 *seqA, *seqB, *hA, *hB, *hbn;
    float  *part, *d1, *d2, *d3;
    cudaGetSymbolAddress((void**)&seqA, g_seqA);
    cudaGetSymbolAddress((void**)&seqB, g_seqB);
    cudaGetSymbolAddress((void**)&hA,   g_hA);
    cudaGetSymbolAddress((void**)&hB,   g_hB);
    cudaGetSymbolAddress((void**)&hbn,  g_hbn);
    cudaGetSymbolAddress((void**)&part, g_part);
    cudaGetSymbolAddress((void**)&d1,   g_d1);
    cudaGetSymbolAddress((void**)&d2,   g_d2);
    cudaGetSymbolAddress((void**)&d3,   g_d3);

    dim3 grid(WW/TW, HH/TILH, BB);   // (4, 16, 64)

    // ---- layer 1 (Cin=3): x -> seqA (BN applied on write) ----
    lstm_step<3,true ,1><<<grid,128>>>(x, TT*PIX, wx1, wh1, b1, g1,bt1,m1,v1,
                                       nullptr, hB, seqA, TT*PIX);
    for (int t = 1; t < TT; t++) {
        const float4* hin  = (t & 1) ? hB : hA;
        float4*       hout = (t & 1) ? hA : hB;
        lstm_step<3,false,1><<<grid,128>>>(x + (long)t*PIX*3, TT*PIX, wx1, wh1, b1,
                                           g1,bt1,m1,v1, hin, hout,
                                           seqA + (long)t*PIX, TT*PIX);
    }

    // ---- layer 2 (Cin=4): seqA -> seqB ----
    lstm_step<4,true ,1><<<grid,128>>>((const float*)seqA, TT*PIX, wx2, wh2, b2,
                                       g2,bt2,m2,v2, nullptr, hB, seqB, TT*PIX);
    for (int t = 1; t < TT; t++) {
        const float4* hin  = (t & 1) ? hB : hA;
        float4*       hout = (t & 1) ? hA : hB;
        lstm_step<4,false,1><<<grid,128>>>((const float*)(seqA + (long)t*PIX), TT*PIX,
                                           wx2, wh2, b2, g2,bt2,m2,v2,
                                           hin, hout, seqB + (long)t*PIX, TT*PIX);
    }

    // ---- layer 3 (Cin=4): seqB -> hbn (only final h, BN + leaky relu) ----
    lstm_step<4,true ,0><<<grid,128>>>((const float*)seqB, TT*PIX, wx3, wh3, b3,
                                       g3,bt3,m3,v3, nullptr, hB, nullptr, 0);
    for (int t = 1; t < TT-1; t++) {
        const float4* hin  = (t & 1) ? hB : hA;
        float4*       hout = (t & 1) ? hA : hB;
        lstm_step<4,false,0><<<grid,128>>>((const float*)(seqB + (long)t*PIX), TT*PIX,
                                           wx3, wh3, b3, g3,bt3,m3,v3,
                                           hin, hout, nullptr, 0);
    }
    {
        const int t = TT-1;  // t = 4: read hA (t&1==0), write hB, emit BN+lrelu
        lstm_step<4,false,2><<<grid,128>>>((const float*)(seqB + (long)t*PIX), TT*PIX,
                                           wx3, wh3, b3, g3,bt3,m3,v3,
                                           hA, hB, hbn, PIX);
    }

    // ---- dense head ----
    gemm1_part<<<NSPLIT,256>>>((const float*)hbn, w_d1, part);
    reduce1<<<32,256>>>(part, b_d1, d1);
    dense_small<<<BB,128>>>(d1, w_d2, b_d2, d2, 128, 1);
    dense_small<<<BB,128>>>(d2, w_d3, b_d3, d3, 128, 1);
    dense_small<<<BB,128>>>(d3, w_o,  b_o,  (float*)d_out, 2, 0);
}